// round 10
// baseline (speedup 1.0000x reference)
#include <cuda_runtime.h>

// Problem-fixed sizes (reference: N=100000, F_IN=512, F_OUT=2).
#define NMAX 100000
#define FOUT 2
#define FIN 512

#define DEG_BLOCKS 120
#define GEMM_BLOCKS 768
#define FUSED_BLOCKS (DEG_BLOCKS + GEMM_BLOCKS)  // 888 = 148 SMs * 6 CTAs

// __device__ globals are zero-initialized at module load; every call restores
// them to zero before finishing (post re-zeros g_deg, head resets scalar +
// ticket), so each graph replay sees identical initial state.
__device__ __align__(16) float g_deg[NMAX];
__device__ __align__(16) float g_dis[NMAX];
__device__ __align__(16) float g_hp4[4][NMAX * FOUT]; // per-quarter partials
__device__ __align__(16) float g_hs[NMAX * FOUT];     // h * dis (gather source)
__device__ __align__(16) float g_acc[NMAX * FOUT];    // self-loop + edge sums
__device__ float g_acc_scalar;
__device__ unsigned int g_ticket;

// ---------------------------------------------------------------------------
// Dummies align the fused kernel onto the profiler's capture slot (idx 3).
__global__ void dummy_kernel() {}

// ---------------------------------------------------------------------------
// K1 (fused, persistent, 6 CTAs/SM): blocks [0, DEG_BLOCKS) do the deg
// segment-sum atomics; blocks [DEG_BLOCKS, 888) run the GEMM.
// GEMM decomposition: 4-warp group per 4 consecutive rows. Warp q covers
// k-quarter q (1 float4 per lane, W slice = 8 regs). Per iteration: 4
// independent LDG.128 (one per row) amortized over 4 rows of FFMA+shuffle,
// so waits per byte halve vs 2-row scheme while regs stay ~42 (occ 6).
__global__ __launch_bounds__(256, 6) void fused_gemm_deg(
        const float* __restrict__ x, const float* __restrict__ W, int n,
        const int* __restrict__ col, const float* __restrict__ w, int E) {
    if ((int)blockIdx.x < DEG_BLOCKS) {
        int t0 = (int)blockIdx.x * 256 + threadIdx.x;
        const int nthr = DEG_BLOCKS * 256;
        int nq = E >> 2;
        for (int q = t0; q < nq; q += nthr) {
            int4 c4 = *(const int4*)(col + q * 4);
            float4 w4 = *(const float4*)(w + q * 4);
            atomicAdd(&g_deg[c4.x], w4.x);
            atomicAdd(&g_deg[c4.y], w4.y);
            atomicAdd(&g_deg[c4.z], w4.z);
            atomicAdd(&g_deg[c4.w], w4.w);
        }
        if (t0 == 0) {
            for (int e = nq * 4; e < E; ++e) atomicAdd(&g_deg[col[e]], w[e]);
        }
        return;
    }
    // --- GEMM: 4-warp group x 4-row tile ---
    int warp = threadIdx.x >> 5;   // 0..7
    int lane = threadIdx.x & 31;
    int grp = warp >> 2;           // 0..1 within block
    int quarter = warp & 3;        // k-quarter
    int q = quarter * 32 + lane;   // this lane's float4 index within a row

    const float4* W4 = (const float4*)W;
    float4 wa = __ldg(W4 + 2 * q), wb = __ldg(W4 + 2 * q + 1);
    float* hp = g_hp4[quarter];

    int g0 = ((int)blockIdx.x - DEG_BLOCKS) * 2 + grp;  // 4-row tile index
    const int gstride = GEMM_BLOCKS * 2;

#define ACCUM(s0, s1, v)                                                   \
    {                                                                      \
        s0 += v.x * wa.x + v.y * wa.z + v.z * wb.x + v.w * wb.z;           \
        s1 += v.x * wa.y + v.y * wa.w + v.z * wb.y + v.w * wb.w;           \
    }
    for (int g = g0; 4 * g < n; g += gstride) {
        int r = 4 * g;  // n % 4 == 0 -> rows r..r+3 all valid
        const float4* xr = (const float4*)(x + (size_t)r * FIN);
        // 4 independent LDG.128, front-batched (rows are consecutive: 8KB tile)
        float4 v0 = __ldg(xr + q);
        float4 v1 = __ldg(xr + q + 128);
        float4 v2 = __ldg(xr + q + 256);
        float4 v3 = __ldg(xr + q + 384);
        float a0 = 0.f, a1 = 0.f, b0 = 0.f, b1 = 0.f;
        float c0 = 0.f, c1 = 0.f, d0 = 0.f, d1 = 0.f;
        ACCUM(a0, a1, v0)
        ACCUM(b0, b1, v1)
        ACCUM(c0, c1, v2)
        ACCUM(d0, d1, v3)
#pragma unroll
        for (int off = 16; off; off >>= 1) {
            a0 += __shfl_down_sync(0xffffffffu, a0, off);
            a1 += __shfl_down_sync(0xffffffffu, a1, off);
            b0 += __shfl_down_sync(0xffffffffu, b0, off);
            b1 += __shfl_down_sync(0xffffffffu, b1, off);
            c0 += __shfl_down_sync(0xffffffffu, c0, off);
            c1 += __shfl_down_sync(0xffffffffu, c1, off);
            d0 += __shfl_down_sync(0xffffffffu, d0, off);
            d1 += __shfl_down_sync(0xffffffffu, d1, off);
        }
        if (lane == 0) {
            *(float2*)(hp + 2 * (r + 0)) = make_float2(a0, a1);
            *(float2*)(hp + 2 * (r + 1)) = make_float2(b0, b1);
            *(float2*)(hp + 2 * (r + 2)) = make_float2(c0, c1);
            *(float2*)(hp + 2 * (r + 3)) = make_float2(d0, d1);
        }
    }
#undef ACCUM
}

// ---------------------------------------------------------------------------
// K2: h = sum of 4 quarter-partials; dis = rsqrt(deg + 1); hs = h*dis;
// acc = hs (self-loop); re-zero g_deg for the next replay.
__global__ void post_kernel(int n) {
    int i = blockIdx.x * blockDim.x + threadIdx.x;
    if (i >= n) return;
    float d = g_deg[i] + 1.0f;  // self-loop weight
    g_deg[i] = 0.0f;            // restore initial state for next call
    float dis = rsqrtf(d);      // d >= 1 always
    g_dis[i] = dis;
    float2 h0 = *(const float2*)(&g_hp4[0][2 * i]);
    float2 h1 = *(const float2*)(&g_hp4[1][2 * i]);
    float2 h2 = *(const float2*)(&g_hp4[2][2 * i]);
    float2 h3 = *(const float2*)(&g_hp4[3][2 * i]);
    float hx = (h0.x + h1.x) + (h2.x + h3.x);
    float hy = (h0.y + h1.y) + (h2.y + h3.y);
    float2 hs = make_float2(hx * dis, hy * dis);
    *(float2*)(g_hs + 2 * i) = hs;
    *(float2*)(g_acc + 2 * i) = hs;
}

// ---------------------------------------------------------------------------
// K3: edge scatter: acc[col] += hs[row] * w. One random 8B gather + one v2
// RED per edge; 4 edges/thread for gather ILP. (~sector-floor bound in L2.)
__global__ __launch_bounds__(256) void edge_kernel(
        const int* __restrict__ row, const int* __restrict__ col,
        const float* __restrict__ w, int E) {
    int t = blockIdx.x * blockDim.x + threadIdx.x;
    int base = t * 4;
    if (base + 3 < E) {
        int4 r4 = *(const int4*)(row + base);
        int4 c4 = *(const int4*)(col + base);
        float4 w4 = *(const float4*)(w + base);
        float2 h0 = __ldg((const float2*)(g_hs + 2 * r4.x));
        float2 h1 = __ldg((const float2*)(g_hs + 2 * r4.y));
        float2 h2 = __ldg((const float2*)(g_hs + 2 * r4.z));
        float2 h3 = __ldg((const float2*)(g_hs + 2 * r4.w));
        asm volatile("red.global.add.v2.f32 [%0], {%1, %2};" ::
                     "l"(g_acc + 2 * c4.x), "f"(h0.x * w4.x), "f"(h0.y * w4.x) : "memory");
        asm volatile("red.global.add.v2.f32 [%0], {%1, %2};" ::
                     "l"(g_acc + 2 * c4.y), "f"(h1.x * w4.y), "f"(h1.y * w4.y) : "memory");
        asm volatile("red.global.add.v2.f32 [%0], {%1, %2};" ::
                     "l"(g_acc + 2 * c4.z), "f"(h2.x * w4.z), "f"(h2.y * w4.z) : "memory");
        asm volatile("red.global.add.v2.f32 [%0], {%1, %2};" ::
                     "l"(g_acc + 2 * c4.w), "f"(h3.x * w4.w), "f"(h3.y * w4.w) : "memory");
    } else {
        for (int e = base; e < E; ++e) {
            int r = row[e], c = col[e];
            float ww = w[e];
            float2 hv = __ldg((const float2*)(g_hs + 2 * r));
            asm volatile("red.global.add.v2.f32 [%0], {%1, %2};" ::
                         "l"(g_acc + 2 * c), "f"(hv.x * ww), "f"(hv.y * ww) : "memory");
        }
    }
}

// ---------------------------------------------------------------------------
// K4: head (+ fused final): relu(dis*acc + b) · fc_w -> g_acc_scalar; last
// block applies sigmoid into d_out and resets scalar state for next replay.
__global__ void head_kernel(const float* __restrict__ bvec,
                            const float* __restrict__ fcw,
                            const float* __restrict__ fcb,
                            float* __restrict__ out, int n, int nblocks) {
    int i = blockIdx.x * blockDim.x + threadIdx.x;
    float p = 0.f;
    if (i < n) {
        float dis = g_dis[i];
        float2 a = *(const float2*)(g_acc + 2 * i);
        float2 fw = *(const float2*)(fcw + 2 * i);
        float v0 = fmaxf(dis * a.x + bvec[0], 0.f);
        float v1 = fmaxf(dis * a.y + bvec[1], 0.f);
        p = v0 * fw.x + v1 * fw.y;
    }
#pragma unroll
    for (int off = 16; off; off >>= 1) p += __shfl_down_sync(0xffffffffu, p, off);
    __shared__ float ws[8];
    __shared__ bool is_last;
    int lane = threadIdx.x & 31, wid = threadIdx.x >> 5;
    if (lane == 0) ws[wid] = p;
    __syncthreads();
    if (wid == 0) {
        p = (lane < (blockDim.x >> 5)) ? ws[lane] : 0.f;
#pragma unroll
        for (int off = 4; off; off >>= 1) p += __shfl_down_sync(0xffffffffu, p, off);
        if (lane == 0) {
            atomicAdd(&g_acc_scalar, p);
            __threadfence();
            unsigned int t = atomicAdd(&g_ticket, 1u);
            is_last = (t == (unsigned int)(nblocks - 1));
        }
    }
    __syncthreads();
    if (is_last && threadIdx.x == 0) {
        float l = g_acc_scalar + fcb[0];
        out[0] = 1.f / (1.f + expf(-l));
        g_acc_scalar = 0.0f;   // restore initial state for next call
        g_ticket = 0u;
    }
}

// ---------------------------------------------------------------------------
extern "C" void kernel_launch(void* const* d_in, const int* in_sizes, int n_in,
                              void* d_out, int out_size) {
    const float* x   = (const float*)d_in[0];      // [N, F_IN]
    const int*   el  = (const int*)d_in[1];        // [2, E] int32 (JAX downcast)
    const float* ea  = (const float*)d_in[2];      // [E]
    const float* W   = (const float*)d_in[3];      // [F_IN, 2]
    const float* b   = (const float*)d_in[4];      // [2]
    const float* fcw = (const float*)d_in[5];      // [2N]
    const float* fcb = (const float*)d_in[6];      // scalar

    int E  = in_sizes[2];
    int n2 = in_sizes[5];
    int n  = n2 / FOUT;

    const int* rowp = el;
    const int* colp = el + E;

    int headB = (n + 255) / 256;

    // 3 dummies keep the fused kernel on the profiler's capture slot (idx 3).
    dummy_kernel<<<1, 32>>>();
    dummy_kernel<<<1, 32>>>();
    dummy_kernel<<<1, 32>>>();
    fused_gemm_deg<<<FUSED_BLOCKS, 256>>>(x, W, n, colp, ea, E);
    post_kernel<<<(n + 255) / 256, 256>>>(n);
    edge_kernel<<<(E / 4 + 255) / 256, 256>>>(rowp, colp, ea, E);
    head_kernel<<<headB, 256>>>(b, fcw, fcb, (float*)d_out, n, headB);
}

// round 11
// speedup vs baseline: 1.2634x; 1.2634x over previous
#include <cuda_runtime.h>

// Problem-fixed sizes (reference: N=100000, F_IN=512, F_OUT=2).
#define NMAX 100000
#define FOUT 2
#define FIN 512

#define DEG_BLOCKS 100
#define GEMM_BLOCKS 640
#define FUSED_BLOCKS (DEG_BLOCKS + GEMM_BLOCKS)  // 740 = 148 SMs * 5 CTAs

// __device__ globals are zero-initialized at module load; every call restores
// them to zero before finishing (post re-zeros g_deg, head resets scalar +
// ticket), so each graph replay sees identical initial state.
__device__ __align__(16) float g_deg[NMAX];
__device__ __align__(16) float g_dis[NMAX];
__device__ __align__(16) float g_hp[2][NMAX * FOUT]; // per-half GEMM partials
__device__ __align__(16) float g_hs[NMAX * FOUT];    // h * dis (gather source)
__device__ __align__(16) float g_acc[NMAX * FOUT];   // self-loop + edge sums
__device__ float g_acc_scalar;
__device__ unsigned int g_ticket;

// ---------------------------------------------------------------------------
// Dummies align the fused kernel onto the profiler's capture slot (idx 3).
__global__ void dummy_kernel() {}

// ---------------------------------------------------------------------------
// K1 (fused, persistent, 5 CTAs/SM): blocks [0, DEG_BLOCKS) do the deg
// segment-sum atomics; blocks [DEG_BLOCKS, 740) run the GEMM.
// GEMM: warp-pair per row (even warp k[0,256), odd warp k[256,512)),
// SOFTWARE-PIPELINED: the next row's 2 LDG.128 issue before the current
// row's FFMA+shuffle, so loads are in flight continuously (duty ~100%)
// instead of the load->stall->compute->repeat pattern that capped DRAM at
// 50%. Prefetch uses an index clamp (SEL) so LDGs stay unconditional.
__global__ __launch_bounds__(256, 5) void fused_gemm_deg(
        const float* __restrict__ x, const float* __restrict__ W, int n,
        const int* __restrict__ col, const float* __restrict__ w, int E) {
    if ((int)blockIdx.x < DEG_BLOCKS) {
        int t0 = (int)blockIdx.x * 256 + threadIdx.x;
        const int nthr = DEG_BLOCKS * 256;
        int nq = E >> 2;
        for (int q = t0; q < nq; q += nthr) {
            int4 c4 = *(const int4*)(col + q * 4);
            float4 w4 = *(const float4*)(w + q * 4);
            atomicAdd(&g_deg[c4.x], w4.x);
            atomicAdd(&g_deg[c4.y], w4.y);
            atomicAdd(&g_deg[c4.z], w4.z);
            atomicAdd(&g_deg[c4.w], w4.w);
        }
        if (t0 == 0) {
            for (int e = nq * 4; e < E; ++e) atomicAdd(&g_deg[col[e]], w[e]);
        }
        return;
    }
    // --- GEMM: pipelined warp-pair per row ---
    int warp = threadIdx.x >> 5;          // 0..7
    int lane = threadIdx.x & 31;
    int half = warp & 1;                  // which k-half of the row
    int row = ((int)blockIdx.x - DEG_BLOCKS) * 4 + (warp >> 1);
    const int rstride = GEMM_BLOCKS * 4;

    // This lane's 2 k-chunks (float4 indices) and their W slices (16 regs).
    int q0 = lane + half * 64;
    int q1 = q0 + 32;
    const float4* W4 = (const float4*)W;
    float4 wa0 = __ldg(W4 + 2 * q0), wb0 = __ldg(W4 + 2 * q0 + 1);
    float4 wa1 = __ldg(W4 + 2 * q1), wb1 = __ldg(W4 + 2 * q1 + 1);
    float* hp = g_hp[half];
    const float4* xb = (const float4*)x;

    if (row >= n) return;

    // prologue load for the first row
    float4 v0 = __ldg(xb + (size_t)row * (FIN / 4) + q0);
    float4 v1 = __ldg(xb + (size_t)row * (FIN / 4) + q1);

#define ACCUM(s0, s1, v, wa, wb)                                           \
    {                                                                      \
        s0 += v.x * wa.x + v.y * wa.z + v.z * wb.x + v.w * wb.z;           \
        s1 += v.x * wa.y + v.y * wa.w + v.z * wb.y + v.w * wb.w;           \
    }
    while (true) {
        int next = row + rstride;
        int next_c = (next < n) ? next : row;   // clamp: load stays valid
        // prefetch next row (unconditional LDG, front-batched)
        float4 p0 = __ldg(xb + (size_t)next_c * (FIN / 4) + q0);
        float4 p1 = __ldg(xb + (size_t)next_c * (FIN / 4) + q1);

        // compute current row from registers loaded last iteration
        float a0 = 0.f, a1 = 0.f;
        ACCUM(a0, a1, v0, wa0, wb0)
        ACCUM(a0, a1, v1, wa1, wb1)
#pragma unroll
        for (int off = 16; off; off >>= 1) {
            a0 += __shfl_down_sync(0xffffffffu, a0, off);
            a1 += __shfl_down_sync(0xffffffffu, a1, off);
        }
        if (lane == 0) {
            *(float2*)(hp + 2 * row) = make_float2(a0, a1);
        }
        if (next >= n) break;
        v0 = p0;
        v1 = p1;
        row = next;
    }
#undef ACCUM
}

// ---------------------------------------------------------------------------
// K2: h = hp0 + hp1; dis = rsqrt(deg + 1); hs = h*dis; acc = hs (self-loop);
// re-zero g_deg for the next replay.
__global__ void post_kernel(int n) {
    int i = blockIdx.x * blockDim.x + threadIdx.x;
    if (i >= n) return;
    float d = g_deg[i] + 1.0f;  // self-loop weight
    g_deg[i] = 0.0f;            // restore initial state for next call
    float dis = rsqrtf(d);      // d >= 1 always
    g_dis[i] = dis;
    float2 h0 = *(const float2*)(&g_hp[0][2 * i]);
    float2 h1 = *(const float2*)(&g_hp[1][2 * i]);
    float2 hs = make_float2((h0.x + h1.x) * dis, (h0.y + h1.y) * dis);
    *(float2*)(g_hs + 2 * i) = hs;
    *(float2*)(g_acc + 2 * i) = hs;
}

// ---------------------------------------------------------------------------
// K3: edge scatter: acc[col] += hs[row] * w. One random 8B gather + one v2
// RED per edge; 4 edges/thread for gather ILP. (~sector-floor bound in L2.)
__global__ __launch_bounds__(256) void edge_kernel(
        const int* __restrict__ row, const int* __restrict__ col,
        const float* __restrict__ w, int E) {
    int t = blockIdx.x * blockDim.x + threadIdx.x;
    int base = t * 4;
    if (base + 3 < E) {
        int4 r4 = *(const int4*)(row + base);
        int4 c4 = *(const int4*)(col + base);
        float4 w4 = *(const float4*)(w + base);
        float2 h0 = __ldg((const float2*)(g_hs + 2 * r4.x));
        float2 h1 = __ldg((const float2*)(g_hs + 2 * r4.y));
        float2 h2 = __ldg((const float2*)(g_hs + 2 * r4.z));
        float2 h3 = __ldg((const float2*)(g_hs + 2 * r4.w));
        asm volatile("red.global.add.v2.f32 [%0], {%1, %2};" ::
                     "l"(g_acc + 2 * c4.x), "f"(h0.x * w4.x), "f"(h0.y * w4.x) : "memory");
        asm volatile("red.global.add.v2.f32 [%0], {%1, %2};" ::
                     "l"(g_acc + 2 * c4.y), "f"(h1.x * w4.y), "f"(h1.y * w4.y) : "memory");
        asm volatile("red.global.add.v2.f32 [%0], {%1, %2};" ::
                     "l"(g_acc + 2 * c4.z), "f"(h2.x * w4.z), "f"(h2.y * w4.z) : "memory");
        asm volatile("red.global.add.v2.f32 [%0], {%1, %2};" ::
                     "l"(g_acc + 2 * c4.w), "f"(h3.x * w4.w), "f"(h3.y * w4.w) : "memory");
    } else {
        for (int e = base; e < E; ++e) {
            int r = row[e], c = col[e];
            float ww = w[e];
            float2 hv = __ldg((const float2*)(g_hs + 2 * r));
            asm volatile("red.global.add.v2.f32 [%0], {%1, %2};" ::
                         "l"(g_acc + 2 * c), "f"(hv.x * ww), "f"(hv.y * ww) : "memory");
        }
    }
}

// ---------------------------------------------------------------------------
// K4: head (+ fused final): relu(dis*acc + b) · fc_w -> g_acc_scalar; last
// block applies sigmoid into d_out and resets scalar state for next replay.
__global__ void head_kernel(const float* __restrict__ bvec,
                            const float* __restrict__ fcw,
                            const float* __restrict__ fcb,
                            float* __restrict__ out, int n, int nblocks) {
    int i = blockIdx.x * blockDim.x + threadIdx.x;
    float p = 0.f;
    if (i < n) {
        float dis = g_dis[i];
        float2 a = *(const float2*)(g_acc + 2 * i);
        float2 fw = *(const float2*)(fcw + 2 * i);
        float v0 = fmaxf(dis * a.x + bvec[0], 0.f);
        float v1 = fmaxf(dis * a.y + bvec[1], 0.f);
        p = v0 * fw.x + v1 * fw.y;
    }
#pragma unroll
    for (int off = 16; off; off >>= 1) p += __shfl_down_sync(0xffffffffu, p, off);
    __shared__ float ws[8];
    __shared__ bool is_last;
    int lane = threadIdx.x & 31, wid = threadIdx.x >> 5;
    if (lane == 0) ws[wid] = p;
    __syncthreads();
    if (wid == 0) {
        p = (lane < (blockDim.x >> 5)) ? ws[lane] : 0.f;
#pragma unroll
        for (int off = 4; off; off >>= 1) p += __shfl_down_sync(0xffffffffu, p, off);
        if (lane == 0) {
            atomicAdd(&g_acc_scalar, p);
            __threadfence();
            unsigned int t = atomicAdd(&g_ticket, 1u);
            is_last = (t == (unsigned int)(nblocks - 1));
        }
    }
    __syncthreads();
    if (is_last && threadIdx.x == 0) {
        float l = g_acc_scalar + fcb[0];
        out[0] = 1.f / (1.f + expf(-l));
        g_acc_scalar = 0.0f;   // restore initial state for next call
        g_ticket = 0u;
    }
}

// ---------------------------------------------------------------------------
extern "C" void kernel_launch(void* const* d_in, const int* in_sizes, int n_in,
                              void* d_out, int out_size) {
    const float* x   = (const float*)d_in[0];      // [N, F_IN]
    const int*   el  = (const int*)d_in[1];        // [2, E] int32 (JAX downcast)
    const float* ea  = (const float*)d_in[2];      // [E]
    const float* W   = (const float*)d_in[3];      // [F_IN, 2]
    const float* b   = (const float*)d_in[4];      // [2]
    const float* fcw = (const float*)d_in[5];      // [2N]
    const float* fcb = (const float*)d_in[6];      // scalar

    int E  = in_sizes[2];
    int n2 = in_sizes[5];
    int n  = n2 / FOUT;

    const int* rowp = el;
    const int* colp = el + E;

    int headB = (n + 255) / 256;

    // 3 dummies keep the fused kernel on the profiler's capture slot (idx 3).
    dummy_kernel<<<1, 32>>>();
    dummy_kernel<<<1, 32>>>();
    dummy_kernel<<<1, 32>>>();
    fused_gemm_deg<<<FUSED_BLOCKS, 256>>>(x, W, n, colp, ea, E);
    post_kernel<<<(n + 255) / 256, 256>>>(n);
    edge_kernel<<<(E / 4 + 255) / 256, 256>>>(rowp, colp, ea, E);
    head_kernel<<<headB, 256>>>(b, fcw, fcb, (float*)d_out, n, headB);
}